// round 6
// baseline (speedup 1.0000x reference)
#include <cuda_runtime.h>
#include <cuda_bf16.h>
#include <cstdint>

#define BB 2
#define NN 512
#define KK 128
#define EE 768
#define NEDGE 1536

// out layout: edge_feature [B,N,N,K] | merge [B,N,E] | delta_pos [B,N,N,3]
#define EF_SIZE   ((size_t)BB*NN*NN*KK)           // 67108864
#define MERGE_OFF EF_SIZE
#define DELTA_OFF (EF_SIZE + (size_t)BB*NN*EE)    // 67895296

// scratch (device globals; no allocation)
__device__ float g_sum[BB*NN*KK];   // row sums of edge_feature over j
__device__ float g_t2[2*KK];        // 2 * t_enc(time_pos[b])
__device__ float g_t02[KK];         // 2 * t_enc(0)

// ---------------------------------------------------------------------------
// Kernel 1: timestep encoder MLP for t(b=0), t(b=1), t=0. One block, 128 thr.
// ---------------------------------------------------------------------------
__global__ void tenc_kernel(const int* __restrict__ time_pos,
                            const float* __restrict__ w1, const float* __restrict__ b1,
                            const float* __restrict__ w2, const float* __restrict__ b2)
{
    __shared__ float e[KK], h[KK];
    int k = threadIdx.x;
    for (int c = 0; c < 3; c++) {
        float tv = (c < 2) ? (float)time_pos[c] : 0.0f;
        int hh = k & 63;
        // freqs[hh] = exp(-log(10000)*hh/64)
        float freq = expf(-9.210340371976184f * (float)hh * (1.0f/64.0f));
        float arg = tv * freq;
        e[k] = (k < 64) ? cosf(arg) : sinf(arg);
        __syncthreads();
        float s = b1[k];
        #pragma unroll 4
        for (int p = 0; p < KK; p++) s = fmaf(e[p], w1[p*KK + k], s);
        float sig = 1.0f / (1.0f + expf(-s));
        h[k] = s * sig;
        __syncthreads();
        float o = b2[k];
        #pragma unroll 4
        for (int p = 0; p < KK; p++) o = fmaf(h[p], w2[p*KK + k], o);
        o *= 2.0f;
        if (c == 0)      g_t2[k]      = o;
        else if (c == 1) g_t2[KK + k] = o;
        else             g_t02[k]     = o;
        __syncthreads();
    }
}

// ---------------------------------------------------------------------------
// Kernel 2: main edge-feature kernel. One block per (b,i) row. 256 threads.
// ---------------------------------------------------------------------------
__global__ __launch_bounds__(256)
void edge_kernel(const float* __restrict__ pos,
                 const int*   __restrict__ nte,
                 const int*   __restrict__ pad,
                 const int*   __restrict__ maa,
                 const int*   __restrict__ mpos,
                 const float* __restrict__ means,
                 const float* __restrict__ stds,
                 const float* __restrict__ mul_w,
                 const float* __restrict__ bias_w,
                 float* __restrict__ out)
{
    const int i = blockIdx.x;
    const int b = blockIdx.y;
    const int tid = threadIdx.x;

    __shared__ float s_px[NN], s_py[NN], s_pz[NN];
    __shared__ float s_x[NN], s_inv[NN];
    __shared__ unsigned char s_flag[NN];      // bit0: pad(j), bit1: maskd
    __shared__ float s_mul[NEDGE], s_bias[NEDGE];
    __shared__ float s_part[8*KK];

    // stage mul_w / bias_w and pos row
    for (int idx = tid; idx < NEDGE; idx += 256) {
        s_mul[idx]  = mul_w[idx];
        s_bias[idx] = bias_w[idx];
    }
    for (int j = tid; j < NN; j += 256) {
        const float* p = pos + (size_t)(b*NN + j)*3;
        s_px[j] = p[0]; s_py[j] = p[1]; s_pz[j] = p[2];
    }
    __syncthreads();

    const float pix = s_px[i], piy = s_py[i], piz = s_pz[i];
    const bool maai = (maa[b*NN + i] != 0);
    const bool mpi  = (mpos[b*NN + i] != 0);

    // per-j scalar precompute
    const size_t pair_base = (size_t)(b*NN + i)*NN;
    for (int j = tid; j < NN; j += 256) {
        float dx = s_px[j] - pix;
        float dy = s_py[j] - piy;
        float dz = s_pz[j] - piz;
        float dist = sqrtf(dx*dx + dy*dy + dz*dz);
        s_inv[j] = 1.0f / (dist + 1e-5f);
        int2 v = ((const int2*)nte)[pair_base + j];
        int i0 = maai ? 0 : v.x;
        int i1 = (maa[b*NN + j] != 0) ? 0 : v.y;
        float mul  = s_mul[i0]  + s_mul[i1];
        float bias = s_bias[i0] + s_bias[i1];
        s_x[j] = fmaf(mul, dist, bias);
        unsigned char f = (pad[b*NN + j] != 0) ? 1u : 0u;
        if (mpi || (mpos[b*NN + j] != 0)) f |= 2u;
        s_flag[j] = f;
    }
    __syncthreads();

    // delta_pos write (contiguous 1536 floats per row)
    {
        float* dout = out + DELTA_OFF + pair_base*3;
        for (int idx = tid; idx < NN*3; idx += 256) {
            int j = idx / 3;
            int c = idx - 3*j;
            float pj = (c == 0) ? s_px[j] : (c == 1) ? s_py[j] : s_pz[j];
            float pi = (c == 0) ? pix     : (c == 1) ? piy     : piz;
            dout[idx] = (pj - pi) * s_inv[j];
        }
    }

    // per-lane Gaussian constants for k = lane*4 + q
    const int lane = tid & 31;
    const int w    = tid >> 5;
    float4 mn = ((const float4*)means)[lane];
    float4 sd = ((const float4*)stds)[lane];
    const float ainv = 0.3989424488f;   // 1/sqrt(2*3.14159)
    float A[4], Bc[4], C[4], T2[4], T0[4], acc[4];
    {
        float sdv[4] = {sd.x, sd.y, sd.z, sd.w};
        float mnv[4] = {mn.x, mn.y, mn.z, mn.w};
        float4 t2v = ((const float4*)g_t2)[b*32 + lane];
        float4 t0v = ((const float4*)g_t02)[lane];
        float t2a[4] = {t2v.x, t2v.y, t2v.z, t2v.w};
        float t0a[4] = {t0v.x, t0v.y, t0v.z, t0v.w};
        #pragma unroll
        for (int q = 0; q < 4; q++) {
            float std = fabsf(sdv[q]) + 0.01f;
            A[q]  = 1.0f / std;
            Bc[q] = -mnv[q] * A[q];
            C[q]  = A[q] * ainv;
            T2[q] = t2a[q];
            T0[q] = t0a[q];
            acc[q] = 0.0f;
        }
    }

    // main loop: each warp walks j with stride 8, lane covers k=lane*4..+3
    float* efrow = out + pair_base*KK;
    for (int j = w; j < NN; j += 8) {
        unsigned f = s_flag[j];
        float4* st = ((float4*)(efrow + (size_t)j*KK)) + lane;
        if (f & 1u) {
            *st = make_float4(0.f, 0.f, 0.f, 0.f);
            continue;
        }
        float x = s_x[j];
        bool md = (f & 2u) != 0;
        float4 r;
        #pragma unroll
        for (int q = 0; q < 4; q++) {
            float t  = md ? T2[q] : T0[q];
            float u  = fmaf(x, A[q], Bc[q]);
            float g  = __expf(-0.5f * u * u);
            float ef = fmaf(g, C[q], t);
            acc[q] += ef;
            (&r.x)[q] = ef;
        }
        *st = r;
    }

    // cross-warp reduction of row sums
    {
        float4* sp = ((float4*)(s_part + w*KK)) + lane;
        *sp = make_float4(acc[0], acc[1], acc[2], acc[3]);
    }
    __syncthreads();
    if (tid < KK) {
        float s = 0.0f;
        #pragma unroll
        for (int ww = 0; ww < 8; ww++) s += s_part[ww*KK + tid];
        g_sum[(size_t)(b*NN + i)*KK + tid] = s;
    }
}

// ---------------------------------------------------------------------------
// Kernel 3: merge = g_sum @ proj_w + proj_b, zeroed on padded i.
// Tiles: 64 rows x 128 cols per block; grid (6, 16).
// ---------------------------------------------------------------------------
__global__ __launch_bounds__(256)
void merge_kernel(const float* __restrict__ pw,
                  const float* __restrict__ pb,
                  const int* __restrict__ pad,
                  float* __restrict__ out)
{
    __shared__ float sA[64][33];
    __shared__ float sW[32][128];
    const int tid = threadIdx.x;
    const int tc = tid & 31;    // 32 col-groups of 4
    const int tr = tid >> 5;    // 8 row-groups of 8
    const int col0 = blockIdx.x * 128;
    const int row0 = blockIdx.y * 64;

    float acc[8][4];
    #pragma unroll
    for (int r = 0; r < 8; r++)
        #pragma unroll
        for (int q = 0; q < 4; q++) acc[r][q] = 0.0f;

    for (int p0 = 0; p0 < KK; p0 += 32) {
        for (int idx = tid; idx < 64*32; idx += 256) {
            int r = idx >> 5, p = idx & 31;
            sA[r][p] = g_sum[(size_t)(row0 + r)*KK + p0 + p];
        }
        for (int idx = tid; idx < 32*128; idx += 256) {
            int p = idx >> 7, c = idx & 127;
            sW[p][c] = pw[(size_t)(p0 + p)*EE + col0 + c];
        }
        __syncthreads();
        #pragma unroll 8
        for (int p = 0; p < 32; p++) {
            float wv[4];
            #pragma unroll
            for (int q = 0; q < 4; q++) wv[q] = sW[p][tc*4 + q];
            #pragma unroll
            for (int r = 0; r < 8; r++) {
                float av = sA[tr*8 + r][p];
                #pragma unroll
                for (int q = 0; q < 4; q++) acc[r][q] = fmaf(av, wv[q], acc[r][q]);
            }
        }
        __syncthreads();
    }

    #pragma unroll
    for (int r = 0; r < 8; r++) {
        int row = row0 + tr*8 + r;
        float pz = (pad[row] != 0) ? 0.0f : 1.0f;
        float4 o;
        #pragma unroll
        for (int q = 0; q < 4; q++)
            (&o.x)[q] = pz * (acc[r][q] + pb[col0 + tc*4 + q]);
        *((float4*)(out + MERGE_OFF + (size_t)row*EE + col0 + tc*4)) = o;
    }
}

// ---------------------------------------------------------------------------
extern "C" void kernel_launch(void* const* d_in, const int* in_sizes, int n_in,
                              void* d_out, int out_size)
{
    const float* pos          = (const float*)d_in[0];
    const int*   nte          = (const int*)d_in[1];
    const int*   pad          = (const int*)d_in[2];
    const int*   maa          = (const int*)d_in[3];
    const int*   mpos         = (const int*)d_in[4];
    const int*   time_pos     = (const int*)d_in[5];
    const float* means        = (const float*)d_in[6];
    const float* stds         = (const float*)d_in[7];
    const float* mul_w        = (const float*)d_in[8];
    const float* bias_w       = (const float*)d_in[9];
    const float* proj_w       = (const float*)d_in[10];
    const float* proj_b       = (const float*)d_in[11];
    const float* t_w1         = (const float*)d_in[12];
    const float* t_b1         = (const float*)d_in[13];
    const float* t_w2         = (const float*)d_in[14];
    const float* t_b2         = (const float*)d_in[15];
    float* out = (float*)d_out;

    tenc_kernel<<<1, 128>>>(time_pos, t_w1, t_b1, t_w2, t_b2);
    edge_kernel<<<dim3(NN, BB), 256>>>(pos, nte, pad, maa, mpos,
                                       means, stds, mul_w, bias_w, out);
    merge_kernel<<<dim3(EE/128, BB*NN/64), 256>>>(proj_w, proj_b, pad, out);
}

// round 10
// speedup vs baseline: 1.5393x; 1.5393x over previous
#include <cuda_runtime.h>
#include <cuda_bf16.h>
#include <cstdint>

#define BB 2
#define NN 512
#define KK 128
#define EE 768
#define NEDGE 1536

// out layout: edge_feature [B,N,N,K] | merge [B,N,E] | delta_pos [B,N,N,3]
#define EF_SIZE   ((size_t)BB*NN*NN*KK)           // 67108864
#define MERGE_OFF EF_SIZE
#define DELTA_OFF (EF_SIZE + (size_t)BB*NN*EE)    // 67895296

// scratch (device globals; no allocation)
__device__ float g_sum[BB*NN*KK];   // row sums of edge_feature over j
__device__ float g_t2[2*KK];        // 2 * t_enc(time_pos[b])
__device__ float g_t02[KK];         // 2 * t_enc(0)

// ---------------------------------------------------------------------------
// Kernel 1: timestep encoder MLP. Grid = 3 blocks (c = b0, b1, t=0),
// 1024 threads each: 8 reduction chunks x 128 output columns.
// ---------------------------------------------------------------------------
__global__ __launch_bounds__(1024)
void tenc_kernel(const int* __restrict__ time_pos,
                 const float* __restrict__ w1, const float* __restrict__ b1,
                 const float* __restrict__ w2, const float* __restrict__ b2)
{
    __shared__ float e[KK], h[KK];
    __shared__ float part[8][KK];
    const int c   = blockIdx.x;
    const int tid = threadIdx.x;
    const int k     = tid & 127;   // output column
    const int chunk = tid >> 7;    // reduction chunk (0..7), 16 terms each

    // sinusoidal embedding
    if (tid < KK) {
        float tv = (c < 2) ? (float)time_pos[c] : 0.0f;
        int hh = tid & 63;
        float freq = expf(-9.210340371976184f * (float)hh * (1.0f/64.0f));
        float arg = tv * freq;
        e[tid] = (tid < 64) ? cosf(arg) : sinf(arg);
    }
    __syncthreads();

    // layer 1: h = silu(e @ w1 + b1)
    {
        float s = 0.0f;
        #pragma unroll
        for (int p0 = 0; p0 < 16; p0++) {
            int p = chunk * 16 + p0;
            s = fmaf(e[p], w1[p*KK + k], s);
        }
        part[chunk][k] = s;
    }
    __syncthreads();
    if (tid < KK) {
        float s = b1[tid];
        #pragma unroll
        for (int q = 0; q < 8; q++) s += part[q][tid];
        float sig = 1.0f / (1.0f + expf(-s));
        h[tid] = s * sig;
    }
    __syncthreads();

    // layer 2: o = 2 * (h @ w2 + b2)
    {
        float s = 0.0f;
        #pragma unroll
        for (int p0 = 0; p0 < 16; p0++) {
            int p = chunk * 16 + p0;
            s = fmaf(h[p], w2[p*KK + k], s);
        }
        part[chunk][k] = s;
    }
    __syncthreads();
    if (tid < KK) {
        float o = b2[tid];
        #pragma unroll
        for (int q = 0; q < 8; q++) o += part[q][tid];
        o *= 2.0f;
        if (c == 0)      g_t2[tid]      = o;
        else if (c == 1) g_t2[KK + tid] = o;
        else             g_t02[tid]     = o;
    }
}

// ---------------------------------------------------------------------------
// Kernel 2: main edge-feature kernel. One block per (b,i) row. 256 threads.
// ---------------------------------------------------------------------------
__global__ __launch_bounds__(256)
void edge_kernel(const float* __restrict__ pos,
                 const int*   __restrict__ nte,
                 const int*   __restrict__ pad,
                 const int*   __restrict__ maa,
                 const int*   __restrict__ mpos,
                 const float* __restrict__ means,
                 const float* __restrict__ stds,
                 const float* __restrict__ mul_w,
                 const float* __restrict__ bias_w,
                 float* __restrict__ out)
{
    const int i = blockIdx.x;
    const int b = blockIdx.y;
    const int tid = threadIdx.x;

    __shared__ float s_px[NN], s_py[NN], s_pz[NN];
    __shared__ float s_x[NN], s_inv[NN];
    __shared__ unsigned char s_flag[NN];      // bit0: pad(j), bit1: maskd
    __shared__ float s_mul[NEDGE], s_bias[NEDGE];
    __shared__ float s_part[8*KK];

    // stage mul_w / bias_w and pos row
    for (int idx = tid; idx < NEDGE; idx += 256) {
        s_mul[idx]  = mul_w[idx];
        s_bias[idx] = bias_w[idx];
    }
    for (int j = tid; j < NN; j += 256) {
        const float* p = pos + (size_t)(b*NN + j)*3;
        s_px[j] = p[0]; s_py[j] = p[1]; s_pz[j] = p[2];
    }
    __syncthreads();

    const float pix = s_px[i], piy = s_py[i], piz = s_pz[i];
    const bool maai = (maa[b*NN + i] != 0);
    const bool mpi  = (mpos[b*NN + i] != 0);

    // per-j scalar precompute
    const size_t pair_base = (size_t)(b*NN + i)*NN;
    for (int j = tid; j < NN; j += 256) {
        float dx = s_px[j] - pix;
        float dy = s_py[j] - piy;
        float dz = s_pz[j] - piz;
        float dist = sqrtf(dx*dx + dy*dy + dz*dz);
        s_inv[j] = 1.0f / (dist + 1e-5f);
        int2 v = ((const int2*)nte)[pair_base + j];
        int i0 = maai ? 0 : v.x;
        int i1 = (maa[b*NN + j] != 0) ? 0 : v.y;
        float mul  = s_mul[i0]  + s_mul[i1];
        float bias = s_bias[i0] + s_bias[i1];
        s_x[j] = fmaf(mul, dist, bias);
        unsigned char f = (pad[b*NN + j] != 0) ? 1u : 0u;
        if (mpi || (mpos[b*NN + j] != 0)) f |= 2u;
        s_flag[j] = f;
    }
    __syncthreads();

    // delta_pos write (contiguous 1536 floats per row)
    {
        float* dout = out + DELTA_OFF + pair_base*3;
        for (int idx = tid; idx < NN*3; idx += 256) {
            int j = idx / 3;
            int c = idx - 3*j;
            float pj = (c == 0) ? s_px[j] : (c == 1) ? s_py[j] : s_pz[j];
            float pi = (c == 0) ? pix     : (c == 1) ? piy     : piz;
            dout[idx] = (pj - pi) * s_inv[j];
        }
    }

    // per-lane Gaussian constants for k = lane*4 + q
    const int lane = tid & 31;
    const int w    = tid >> 5;
    float4 mn = ((const float4*)means)[lane];
    float4 sd = ((const float4*)stds)[lane];
    const float ainv = 0.3989424488f;   // 1/sqrt(2*3.14159)
    float A[4], Bc[4], C[4], T2[4], T0[4], acc[4];
    {
        float sdv[4] = {sd.x, sd.y, sd.z, sd.w};
        float mnv[4] = {mn.x, mn.y, mn.z, mn.w};
        float4 t2v = ((const float4*)g_t2)[b*32 + lane];
        float4 t0v = ((const float4*)g_t02)[lane];
        float t2a[4] = {t2v.x, t2v.y, t2v.z, t2v.w};
        float t0a[4] = {t0v.x, t0v.y, t0v.z, t0v.w};
        #pragma unroll
        for (int q = 0; q < 4; q++) {
            float std = fabsf(sdv[q]) + 0.01f;
            A[q]  = 1.0f / std;
            Bc[q] = -mnv[q] * A[q];
            C[q]  = A[q] * ainv;
            T2[q] = t2a[q];
            T0[q] = t0a[q];
            acc[q] = 0.0f;
        }
    }

    // main loop: each warp walks j with stride 8, lane covers k=lane*4..+3
    float* efrow = out + pair_base*KK;
    for (int j = w; j < NN; j += 8) {
        unsigned f = s_flag[j];
        float4* st = ((float4*)(efrow + (size_t)j*KK)) + lane;
        if (f & 1u) {
            *st = make_float4(0.f, 0.f, 0.f, 0.f);
            continue;
        }
        float x = s_x[j];
        bool md = (f & 2u) != 0;
        float4 r;
        #pragma unroll
        for (int q = 0; q < 4; q++) {
            float t  = md ? T2[q] : T0[q];
            float u  = fmaf(x, A[q], Bc[q]);
            float g  = __expf(-0.5f * u * u);
            float ef = fmaf(g, C[q], t);
            acc[q] += ef;
            (&r.x)[q] = ef;
        }
        *st = r;
    }

    // cross-warp reduction of row sums
    {
        float4* sp = ((float4*)(s_part + w*KK)) + lane;
        *sp = make_float4(acc[0], acc[1], acc[2], acc[3]);
    }
    __syncthreads();
    if (tid < KK) {
        float s = 0.0f;
        #pragma unroll
        for (int ww = 0; ww < 8; ww++) s += s_part[ww*KK + tid];
        g_sum[(size_t)(b*NN + i)*KK + tid] = s;
    }
}

// ---------------------------------------------------------------------------
// Kernel 3: merge = g_sum @ proj_w + proj_b, zeroed on padded i.
// Tiles: 64 rows x 128 cols per block; grid (6, 16).
// ---------------------------------------------------------------------------
__global__ __launch_bounds__(256)
void merge_kernel(const float* __restrict__ pw,
                  const float* __restrict__ pb,
                  const int* __restrict__ pad,
                  float* __restrict__ out)
{
    __shared__ float sA[64][33];
    __shared__ float sW[32][128];
    const int tid = threadIdx.x;
    const int tc = tid & 31;    // 32 col-groups of 4
    const int tr = tid >> 5;    // 8 row-groups of 8
    const int col0 = blockIdx.x * 128;
    const int row0 = blockIdx.y * 64;

    float acc[8][4];
    #pragma unroll
    for (int r = 0; r < 8; r++)
        #pragma unroll
        for (int q = 0; q < 4; q++) acc[r][q] = 0.0f;

    for (int p0 = 0; p0 < KK; p0 += 32) {
        for (int idx = tid; idx < 64*32; idx += 256) {
            int r = idx >> 5, p = idx & 31;
            sA[r][p] = g_sum[(size_t)(row0 + r)*KK + p0 + p];
        }
        for (int idx = tid; idx < 32*128; idx += 256) {
            int p = idx >> 7, c = idx & 127;
            sW[p][c] = pw[(size_t)(p0 + p)*EE + col0 + c];
        }
        __syncthreads();
        #pragma unroll 8
        for (int p = 0; p < 32; p++) {
            float wv[4];
            #pragma unroll
            for (int q = 0; q < 4; q++) wv[q] = sW[p][tc*4 + q];
            #pragma unroll
            for (int r = 0; r < 8; r++) {
                float av = sA[tr*8 + r][p];
                #pragma unroll
                for (int q = 0; q < 4; q++) acc[r][q] = fmaf(av, wv[q], acc[r][q]);
            }
        }
        __syncthreads();
    }

    #pragma unroll
    for (int r = 0; r < 8; r++) {
        int row = row0 + tr*8 + r;
        float pz = (pad[row] != 0) ? 0.0f : 1.0f;
        float4 o;
        #pragma unroll
        for (int q = 0; q < 4; q++)
            (&o.x)[q] = pz * (acc[r][q] + pb[col0 + tc*4 + q]);
        *((float4*)(out + MERGE_OFF + (size_t)row*EE + col0 + tc*4)) = o;
    }
}

// ---------------------------------------------------------------------------
extern "C" void kernel_launch(void* const* d_in, const int* in_sizes, int n_in,
                              void* d_out, int out_size)
{
    const float* pos          = (const float*)d_in[0];
    const int*   nte          = (const int*)d_in[1];
    const int*   pad          = (const int*)d_in[2];
    const int*   maa          = (const int*)d_in[3];
    const int*   mpos         = (const int*)d_in[4];
    const int*   time_pos     = (const int*)d_in[5];
    const float* means        = (const float*)d_in[6];
    const float* stds         = (const float*)d_in[7];
    const float* mul_w        = (const float*)d_in[8];
    const float* bias_w       = (const float*)d_in[9];
    const float* proj_w       = (const float*)d_in[10];
    const float* proj_b       = (const float*)d_in[11];
    const float* t_w1         = (const float*)d_in[12];
    const float* t_b1         = (const float*)d_in[13];
    const float* t_w2         = (const float*)d_in[14];
    const float* t_b2         = (const float*)d_in[15];
    float* out = (float*)d_out;

    tenc_kernel<<<3, 1024>>>(time_pos, t_w1, t_b1, t_w2, t_b2);
    edge_kernel<<<dim3(NN, BB), 256>>>(pos, nte, pad, maa, mpos,
                                       means, stds, mul_w, bias_w, out);
    merge_kernel<<<dim3(EE/128, BB*NN/64), 256>>>(proj_w, proj_b, pad, out);
}